// round 6
// baseline (speedup 1.0000x reference)
#include <cuda_runtime.h>
#include <cstdint>

// Problem constants (match reference)
#define IMG_H 256
#define IMG_W 256
#define NB    8
#define NP    65536
#define EPSF  1e-5f

#define HW  (IMG_H * IMG_W)
#define BHW (NB * HW)              // 524288
#define BN  (NB * NP)              // 524288

// z encoding: enc(z) = ~bits(z). For positive z, enc is strictly DEcreasing,
// so max(enc) == min(z), and 0 is a natural "empty" value -> zero-init device
// globals cover the first call; finish_kernel re-zeros for graph replays.
__device__ unsigned int g_pm[BHW];     // per-pixel max of enc(z); 0 = empty
__device__ unsigned int g_zenc[BHW];   // 5x5 max-filtered enc (fully overwritten)

// Interleaved (wz, w) accumulator with 4-float4 front/back padding so that
// vector atomics whose zero-weight pad lanes fall outside the image (they add
// exactly +0.0f) can never touch memory outside this array.
__device__ float4 g_dw4[BHW / 2 + 8];  // [4 pad | BHW/2 data | 4 pad]
#define DW_BASE ((float2*)g_dw4 + 8)   // float2 view of data region (16B aligned)

// Compacted visible-point records: (x, y, z, batch-as-float-bits)
__device__ float4       g_vlist[BN];
__device__ unsigned int g_nvis;        // zero-init'd; reset by finish_kernel

// ---------------------------------------------------------------------------
// Pass 1: per-pixel scatter-min, 4 points per thread (3x LDG.128)
// ---------------------------------------------------------------------------
__global__ void scatter_pm_kernel(const float4* __restrict__ pts4) {
    int idx = blockIdx.x * blockDim.x + threadIdx.x;
    if (idx >= BN / 4) return;
    float4 a = pts4[3 * idx + 0];
    float4 b = pts4[3 * idx + 1];
    float4 c = pts4[3 * idx + 2];
    unsigned int* pm = g_pm + (idx >> 14) * HW;   // batch = (4*idx)/NP

    float xs[4] = {a.x, a.w, b.z, c.y};
    float ys[4] = {a.y, b.x, b.w, c.z};
    float zs[4] = {a.z, b.y, c.x, c.w};
    #pragma unroll
    for (int k = 0; k < 4; k++) {
        int px = (int)rintf(xs[k]);   // round-half-even == jnp.round
        int py = (int)rintf(ys[k]);
        if (px < 0 || px >= IMG_W || py < 0 || py >= IMG_H) continue;
        atomicMax(&pm[py * IMG_W + px], ~__float_as_uint(zs[k]));
    }
}

// ---------------------------------------------------------------------------
// Pass 2: 5x5 max-filter (== 5x5 min-erosion of z), separable in smem tiles
// ---------------------------------------------------------------------------
#define TILE 32
__global__ void minfilter_kernel() {
    __shared__ unsigned int s[36][36 + 1];
    __shared__ unsigned int h[36][TILE + 1];

    int b  = blockIdx.z;
    int ox = blockIdx.x * TILE;
    int oy = blockIdx.y * TILE;
    const unsigned int* pm = g_pm + b * HW;
    int t = threadIdx.y * blockDim.x + threadIdx.x;  // 256 threads

    for (int i = t; i < 36 * 36; i += 256) {
        int r = i / 36, c = i % 36;
        int gy = oy + r - 2, gx = ox + c - 2;
        unsigned int v = 0;  // OOB -> empty (identity for max)
        if (gy >= 0 && gy < IMG_H && gx >= 0 && gx < IMG_W) v = pm[gy * IMG_W + gx];
        s[r][c] = v;
    }
    __syncthreads();

    for (int i = t; i < 36 * TILE; i += 256) {
        int r = i / TILE, c = i % TILE;
        unsigned int v = s[r][c];
        v = max(v, s[r][c + 1]);
        v = max(v, s[r][c + 2]);
        v = max(v, s[r][c + 3]);
        v = max(v, s[r][c + 4]);
        h[r][c] = v;
    }
    __syncthreads();

    unsigned int* zo = g_zenc + b * HW;
    for (int i = t; i < TILE * TILE; i += 256) {
        int r = i / TILE, c = i % TILE;
        unsigned int v = h[r][c];
        v = max(v, h[r + 1][c]);
        v = max(v, h[r + 2][c]);
        v = max(v, h[r + 3][c]);
        v = max(v, h[r + 4][c]);
        zo[(oy + r) * IMG_W + (ox + c)] = v;
    }
}

// ---------------------------------------------------------------------------
// Pass 3: visibility (4 points/thread) + compaction of visible records
// ---------------------------------------------------------------------------
__global__ void vis_compact_kernel(const float4* __restrict__ pts4,
                                   const float* __restrict__ thr_p,
                                   float4* __restrict__ vis_out4) {
    int idx = blockIdx.x * blockDim.x + threadIdx.x;
    if (idx >= BN / 4) return;
    float4 a = pts4[3 * idx + 0];
    float4 b = pts4[3 * idx + 1];
    float4 c = pts4[3 * idx + 2];
    float thr = __ldg(thr_p);
    int bb = idx >> 14;
    const unsigned int* ze = g_zenc + bb * HW;

    float xs[4] = {a.x, a.w, b.z, c.y};
    float ys[4] = {a.y, b.x, b.w, c.z};
    float zs[4] = {a.z, b.y, c.x, c.w};
    float visf[4];
    #pragma unroll
    for (int k = 0; k < 4; k++) {
        int px = (int)rintf(xs[k]);
        int py = (int)rintf(ys[k]);
        bool in_img = (px >= 0) && (px < IMG_W) && (py >= 0) && (py < IMG_H);
        bool vis = false;
        if (in_img) {
            float zmin = __uint_as_float(~ze[py * IMG_W + px]);
            vis = (zs[k] <= zmin + thr);
        }
        visf[k] = vis ? 1.0f : 0.0f;
        if (vis) {
            unsigned int slot = atomicAdd(&g_nvis, 1u);
            g_vlist[slot] = make_float4(xs[k], ys[k], zs[k], __int_as_float(bb));
        }
    }
    vis_out4[idx] = make_float4(visf[0], visf[1], visf[2], visf[3]);
}

// ---------------------------------------------------------------------------
// Pass 4: dense splat over compacted visible points using float4 vector
// atomics. Each 7-wide row is covered by 4 aligned float4 (RED.128) ops over
// an 8-pixel even-aligned window; the single out-of-patch pad lane (and any
// out-of-image lane on the border path) gets weight 0 -> adds +0.0f, which is
// numerically invisible; array padding absorbs the physical overreach.
// ---------------------------------------------------------------------------
__global__ void splat_dense_kernel() {
    int cnt = (int)g_nvis;
    int stride = gridDim.x * blockDim.x;
    for (int i = blockIdx.x * blockDim.x + threadIdx.x; i < cnt; i += stride) {
        float4 r = g_vlist[i];
        float x = r.x, y = r.y, z = r.z;
        int bb = __float_as_int(r.w);
        int px = (int)rintf(x);
        int py = (int)rintf(y);
        float2* base = DW_BASE + bb * HW;

        int jstart = (px - 3) & ~1;           // even-aligned 8-col window
        bool interior = (px >= 4) && (px <= IMG_W - 5) &&
                        (py >= 3) && (py <= IMG_H - 4);

        // Per-column dx and in-range mask for the 8-column window
        float dxs[8];
        bool  inc[8];
        #pragma unroll
        for (int cidx = 0; cidx < 8; cidx++) {
            int jj = jstart + cidx;
            dxs[cidx] = x - (float)jj;
            bool in_patch = (jj >= px - 3) && (jj <= px + 3);
            inc[cidx] = interior ? in_patch
                                 : (in_patch && jj >= 0 && jj < IMG_W);
        }

        #pragma unroll
        for (int di = -3; di <= 3; di++) {
            int ii = py + di;
            if (!interior && (ii < 0 || ii >= IMG_H)) continue;
            float dy = y - (float)ii;
            float dy2 = dy * dy;
            float2* rowp = base + ii * IMG_W + jstart;
            #pragma unroll
            for (int k = 0; k < 4; k++) {
                float w0 = inc[2 * k]     ? 1.0f / (dxs[2 * k]     * dxs[2 * k]     + dy2 + EPSF) : 0.0f;
                float w1 = inc[2 * k + 1] ? 1.0f / (dxs[2 * k + 1] * dxs[2 * k + 1] + dy2 + EPSF) : 0.0f;
                atomicAdd((float4*)(rowp + 2 * k),
                          make_float4(w0 * z, w0, w1 * z, w1));
            }
        }
    }
}

// ---------------------------------------------------------------------------
// Pass 5: de-interleave accumulator into output planes + reset all scratch
// ---------------------------------------------------------------------------
__global__ void finish_kernel(float* __restrict__ out) {
    int i = blockIdx.x * blockDim.x + threadIdx.x;  // one thread = 4 pixels
    if (i >= BHW / 4) return;
    const float4* dw = (const float4*)DW_BASE;      // 16B aligned
    float4 f0 = dw[2 * i];                          // (wz0, w0, wz1, w1)
    float4 f1 = dw[2 * i + 1];                      // (wz2, w2, wz3, w3)
    ((float4*)out)[i]                = make_float4(f0.x, f0.z, f1.x, f1.z);  // depth
    ((float4*)(out + BHW))[i]        = make_float4(f0.y, f0.w, f1.y, f1.w);  // weight
    ((float4*)DW_BASE)[2 * i]        = make_float4(0.f, 0.f, 0.f, 0.f);
    ((float4*)DW_BASE)[2 * i + 1]    = make_float4(0.f, 0.f, 0.f, 0.f);
    ((uint4*)g_pm)[i]                = make_uint4(0u, 0u, 0u, 0u);
    if (i == 0) g_nvis = 0u;
}

// ---------------------------------------------------------------------------
extern "C" void kernel_launch(void* const* d_in, const int* in_sizes, int n_in,
                              void* d_out, int out_size) {
    const float* pts = (const float*)d_in[0];   // [B, N, 3]
    const float* thr = (const float*)d_in[1];   // scalar
    float* out = (float*)d_out;                 // [depth | weight | is_visible]

    const int T = 256;
    scatter_pm_kernel<<<(BN / 4 + T - 1) / T, T>>>((const float4*)pts);
    dim3 fgrid(IMG_W / TILE, IMG_H / TILE, NB);
    minfilter_kernel<<<fgrid, dim3(32, 8)>>>();
    vis_compact_kernel<<<(BN / 4 + T - 1) / T, T>>>((const float4*)pts, thr,
                                                    (float4*)(out + 2 * BHW));
    splat_dense_kernel<<<1024, T>>>();
    finish_kernel<<<(BHW / 4 + T - 1) / T, T>>>(out);
}

// round 8
// speedup vs baseline: 1.2449x; 1.2449x over previous
#include <cuda_runtime.h>
#include <cstdint>

// Problem constants (match reference)
#define IMG_H 256
#define IMG_W 256
#define NB    8
#define NP    65536
#define EPSF  1e-5f

#define HW  (IMG_H * IMG_W)
#define BHW (NB * HW)              // 524288
#define BN  (NB * NP)              // 524288

// z encoding: enc(z) = ~bits(z). For positive z, enc is strictly DEcreasing,
// so max(enc) == min(z), and 0 is a natural "empty" value -> zero-init device
// globals cover the first call; finish_kernel re-zeros for graph replays.
__device__ unsigned int g_pm[BHW];     // per-pixel max of enc(z); 0 = empty
__device__ unsigned int g_zenc[BHW];   // 5x5 max-filtered enc (fully overwritten)

// Interleaved (wz, w) accumulator with 4-float4 front/back padding so vector
// atomics whose zero-weight pad lanes fall outside a row can never leave the
// array (they add exactly +0.0f wherever they land).
__device__ float4 g_dw4[BHW / 2 + 8];  // [4 pad | BHW/2 data | 4 pad]
#define DW_BASE ((float2*)g_dw4 + 8)   // float2 view of data region (16B aligned)

// Compacted visible-point records: (x, y, z, batch-as-float-bits)
__device__ float4       g_vlist[BN];
__device__ unsigned int g_nvis;        // zero-init'd; reset by finish_kernel

// ---------------------------------------------------------------------------
// Pass 1: per-pixel scatter-min, 4 points per thread (3x LDG.128)
// ---------------------------------------------------------------------------
__global__ void scatter_pm_kernel(const float4* __restrict__ pts4) {
    int idx = blockIdx.x * blockDim.x + threadIdx.x;
    if (idx >= BN / 4) return;
    float4 a = pts4[3 * idx + 0];
    float4 b = pts4[3 * idx + 1];
    float4 c = pts4[3 * idx + 2];
    unsigned int* pm = g_pm + (idx >> 14) * HW;   // batch = (4*idx)/NP

    float xs[4] = {a.x, a.w, b.z, c.y};
    float ys[4] = {a.y, b.x, b.w, c.z};
    float zs[4] = {a.z, b.y, c.x, c.w};
    #pragma unroll
    for (int k = 0; k < 4; k++) {
        int px = (int)rintf(xs[k]);   // round-half-even == jnp.round
        int py = (int)rintf(ys[k]);
        if (px < 0 || px >= IMG_W || py < 0 || py >= IMG_H) continue;
        atomicMax(&pm[py * IMG_W + px], ~__float_as_uint(zs[k]));
    }
}

// ---------------------------------------------------------------------------
// Pass 2: 5x5 max-filter (== 5x5 min-erosion of z), separable in smem tiles
// ---------------------------------------------------------------------------
#define TILE 32
__global__ void minfilter_kernel() {
    __shared__ unsigned int s[36][36 + 1];
    __shared__ unsigned int h[36][TILE + 1];

    int b  = blockIdx.z;
    int ox = blockIdx.x * TILE;
    int oy = blockIdx.y * TILE;
    const unsigned int* pm = g_pm + b * HW;
    int t = threadIdx.y * blockDim.x + threadIdx.x;  // 256 threads

    for (int i = t; i < 36 * 36; i += 256) {
        int r = i / 36, c = i % 36;
        int gy = oy + r - 2, gx = ox + c - 2;
        unsigned int v = 0;  // OOB -> empty (identity for max)
        if (gy >= 0 && gy < IMG_H && gx >= 0 && gx < IMG_W) v = pm[gy * IMG_W + gx];
        s[r][c] = v;
    }
    __syncthreads();

    for (int i = t; i < 36 * TILE; i += 256) {
        int r = i / TILE, c = i % TILE;
        unsigned int v = s[r][c];
        v = max(v, s[r][c + 1]);
        v = max(v, s[r][c + 2]);
        v = max(v, s[r][c + 3]);
        v = max(v, s[r][c + 4]);
        h[r][c] = v;
    }
    __syncthreads();

    unsigned int* zo = g_zenc + b * HW;
    for (int i = t; i < TILE * TILE; i += 256) {
        int r = i / TILE, c = i % TILE;
        unsigned int v = h[r][c];
        v = max(v, h[r + 1][c]);
        v = max(v, h[r + 2][c]);
        v = max(v, h[r + 3][c]);
        v = max(v, h[r + 4][c]);
        zo[(oy + r) * IMG_W + (ox + c)] = v;
    }
}

// ---------------------------------------------------------------------------
// Pass 3: visibility (4 points/thread) + block-aggregated compaction.
// One global atomic per BLOCK (512 total) instead of one per visible point
// (~52K serialized on a single address). Record order is irrelevant: the
// splat's atomics commute.
// ---------------------------------------------------------------------------
__global__ void vis_compact_kernel(const float4* __restrict__ pts4,
                                   const float* __restrict__ thr_p,
                                   float4* __restrict__ vis_out4) {
    // Grid is sized EXACTLY BN/4 threads: no early returns before barriers.
    int idx = blockIdx.x * blockDim.x + threadIdx.x;
    float4 a = pts4[3 * idx + 0];
    float4 b = pts4[3 * idx + 1];
    float4 c = pts4[3 * idx + 2];
    float thr = __ldg(thr_p);
    int bb = idx >> 14;
    const unsigned int* ze = g_zenc + bb * HW;

    float xs[4] = {a.x, a.w, b.z, c.y};
    float ys[4] = {a.y, b.x, b.w, c.z};
    float zs[4] = {a.z, b.y, c.x, c.w};
    bool vis[4];
    unsigned int cnt = 0;
    #pragma unroll
    for (int k = 0; k < 4; k++) {
        int px = (int)rintf(xs[k]);
        int py = (int)rintf(ys[k]);
        bool in_img = (px >= 0) && (px < IMG_W) && (py >= 0) && (py < IMG_H);
        bool v = false;
        if (in_img) {
            float zmin = __uint_as_float(~ze[py * IMG_W + px]);
            v = (zs[k] <= zmin + thr);
        }
        vis[k] = v;
        cnt += v ? 1u : 0u;
    }
    vis_out4[idx] = make_float4(vis[0] ? 1.f : 0.f, vis[1] ? 1.f : 0.f,
                                vis[2] ? 1.f : 0.f, vis[3] ? 1.f : 0.f);

    // warp inclusive scan of cnt
    unsigned int lane = threadIdx.x & 31u;
    unsigned int warp = threadIdx.x >> 5;
    unsigned int incl = cnt;
    #pragma unroll
    for (int d = 1; d < 32; d <<= 1) {
        unsigned int v = __shfl_up_sync(0xFFFFFFFFu, incl, d);
        if (lane >= d) incl += v;
    }
    unsigned int excl = incl - cnt;

    __shared__ unsigned int woff[8];
    __shared__ unsigned int blk_base;
    if (lane == 31u) woff[warp] = incl;   // warp total
    __syncthreads();
    if (threadIdx.x == 0) {
        unsigned int s = 0;
        #pragma unroll
        for (int w = 0; w < 8; w++) { unsigned int t = woff[w]; woff[w] = s; s += t; }
        blk_base = atomicAdd(&g_nvis, s);
    }
    __syncthreads();

    unsigned int slot = blk_base + woff[warp] + excl;
    #pragma unroll
    for (int k = 0; k < 4; k++) {
        if (vis[k]) {
            g_vlist[slot++] = make_float4(xs[k], ys[k], zs[k], __int_as_float(bb));
        }
    }
}

// ---------------------------------------------------------------------------
// Pass 4: dense splat, ONE THREAD PER (point, patch-row): 8 threads per point
// (8th lane idle) -> ~7x more warps in flight than point-per-thread, which is
// what the latency-bound profile (occ 26%, issue 22%) needs. Each row is 4
// aligned float4 (RED.128) ops over an even-aligned 8-col window; zero-weight
// lanes add +0.0f and array padding absorbs physical overreach.
// ---------------------------------------------------------------------------
__global__ void splat_row_kernel() {
    int cnt = (int)g_nvis;
    int total = cnt << 3;               // 8 slots per point
    int stride = gridDim.x * blockDim.x;
    for (int i = blockIdx.x * blockDim.x + threadIdx.x; i < total; i += stride) {
        int row = i & 7;
        if (row == 7) continue;         // idle lane
        int point = i >> 3;
        float4 r = __ldg(&g_vlist[point]);   // 8 lanes share the same 16B line
        float x = r.x, y = r.y, z = r.z;
        int bb = __float_as_int(r.w);
        int px = (int)rintf(x);
        int py = (int)rintf(y);

        int ii = py + row - 3;
        if (ii < 0 || ii >= IMG_H) continue;

        float dy = y - (float)ii;
        float dy2 = dy * dy;
        int jstart = (px - 3) & ~1;     // even-aligned 8-col window
        float2* rowp = DW_BASE + bb * HW + ii * IMG_W + jstart;

        float ww[8];
        #pragma unroll
        for (int cc = 0; cc < 8; cc++) {
            int jj = jstart + cc;
            float dx = x - (float)jj;
            bool ok = (jj >= px - 3) && (jj <= px + 3) && (jj >= 0) && (jj < IMG_W);
            ww[cc] = ok ? 1.0f / (dx * dx + dy2 + EPSF) : 0.0f;
        }
        #pragma unroll
        for (int k = 0; k < 4; k++) {
            atomicAdd((float4*)(rowp + 2 * k),
                      make_float4(ww[2 * k] * z, ww[2 * k],
                                  ww[2 * k + 1] * z, ww[2 * k + 1]));
        }
    }
}

// ---------------------------------------------------------------------------
// Pass 5: de-interleave accumulator (8 px/thread, MLP=4) + reset all scratch
// ---------------------------------------------------------------------------
__global__ void finish_kernel(float* __restrict__ out) {
    int i = blockIdx.x * blockDim.x + threadIdx.x;  // one thread = 8 pixels
    if (i >= BHW / 8) return;
    const float4* dw = (const float4*)DW_BASE;      // 16B aligned
    float4 f0 = dw[4 * i + 0];
    float4 f1 = dw[4 * i + 1];
    float4 f2 = dw[4 * i + 2];
    float4 f3 = dw[4 * i + 3];
    ((float4*)out)[2 * i + 0]         = make_float4(f0.x, f0.z, f1.x, f1.z);  // depth
    ((float4*)out)[2 * i + 1]         = make_float4(f2.x, f2.z, f3.x, f3.z);
    ((float4*)(out + BHW))[2 * i + 0] = make_float4(f0.y, f0.w, f1.y, f1.w);  // weight
    ((float4*)(out + BHW))[2 * i + 1] = make_float4(f2.y, f2.w, f3.y, f3.w);
    float4 zf = make_float4(0.f, 0.f, 0.f, 0.f);
    ((float4*)DW_BASE)[4 * i + 0] = zf;
    ((float4*)DW_BASE)[4 * i + 1] = zf;
    ((float4*)DW_BASE)[4 * i + 2] = zf;
    ((float4*)DW_BASE)[4 * i + 3] = zf;
    uint4 zu = make_uint4(0u, 0u, 0u, 0u);
    ((uint4*)g_pm)[2 * i + 0] = zu;
    ((uint4*)g_pm)[2 * i + 1] = zu;
    if (i == 0) g_nvis = 0u;
}

// ---------------------------------------------------------------------------
extern "C" void kernel_launch(void* const* d_in, const int* in_sizes, int n_in,
                              void* d_out, int out_size) {
    const float* pts = (const float*)d_in[0];   // [B, N, 3]
    const float* thr = (const float*)d_in[1];   // scalar
    float* out = (float*)d_out;                 // [depth | weight | is_visible]

    const int T = 256;
    scatter_pm_kernel<<<BN / 4 / T, T>>>((const float4*)pts);
    dim3 fgrid(IMG_W / TILE, IMG_H / TILE, NB);
    minfilter_kernel<<<fgrid, dim3(32, 8)>>>();
    vis_compact_kernel<<<BN / 4 / T, T>>>((const float4*)pts, thr,
                                          (float4*)(out + 2 * BHW));
    splat_row_kernel<<<2048, T>>>();
    finish_kernel<<<BHW / 8 / T, T>>>(out);
}

// round 9
// speedup vs baseline: 1.4463x; 1.1617x over previous
#include <cuda_runtime.h>
#include <cstdint>

// Problem constants (match reference)
#define IMG_H 256
#define IMG_W 256
#define NB    8
#define NP    65536
#define EPSF  1e-5f

#define HW  (IMG_H * IMG_W)
#define BHW (NB * HW)              // 524288
#define BN  (NB * NP)              // 524288

// z encoding: enc(z) = ~bits(z). For positive z, enc is strictly DEcreasing,
// so max(enc) == min(z), and 0 is a natural "empty" value -> zero-init device
// globals cover the first call; scratch is re-zeroed each call for replays.
__device__ unsigned int g_pm[BHW];     // per-pixel max of enc(z); 0 = empty
__device__ unsigned int g_zenc[BHW];   // 5x5 max-filtered enc (fully overwritten)

// Interleaved (wz, w) accumulator with 4-float4 front/back padding so vector
// atomics whose zero-weight pad lanes fall outside a row can never leave the
// array (they add exactly +0.0f wherever they land).
__device__ float4 g_dw4[BHW / 2 + 8];  // [4 pad | BHW/2 data | 4 pad]
#define DW_BASE ((float2*)g_dw4 + 8)   // float2 view of data region (16B aligned)

// Compacted visible-point records: (x, y, z, batch-as-float-bits)
__device__ float4       g_vlist[BN];
__device__ unsigned int g_nvis;        // zero-init'd; reset by finish_kernel

__device__ __forceinline__ float fast_rcp(float x) {
    float r;
    asm("rcp.approx.f32 %0, %1;" : "=f"(r) : "f"(x));
    return r;
}

// ---------------------------------------------------------------------------
// Pass 1: per-pixel scatter-min, 4 points per thread (3x LDG.128)
// ---------------------------------------------------------------------------
__global__ void scatter_pm_kernel(const float4* __restrict__ pts4) {
    int idx = blockIdx.x * blockDim.x + threadIdx.x;
    if (idx >= BN / 4) return;
    float4 a = pts4[3 * idx + 0];
    float4 b = pts4[3 * idx + 1];
    float4 c = pts4[3 * idx + 2];
    unsigned int* pm = g_pm + (idx >> 14) * HW;   // batch = (4*idx)/NP

    float xs[4] = {a.x, a.w, b.z, c.y};
    float ys[4] = {a.y, b.x, b.w, c.z};
    float zs[4] = {a.z, b.y, c.x, c.w};
    #pragma unroll
    for (int k = 0; k < 4; k++) {
        int px = (int)rintf(xs[k]);   // round-half-even == jnp.round
        int py = (int)rintf(ys[k]);
        if (px < 0 || px >= IMG_W || py < 0 || py >= IMG_H) continue;
        atomicMax(&pm[py * IMG_W + px], ~__float_as_uint(zs[k]));
    }
}

// ---------------------------------------------------------------------------
// Pass 2: 5x5 max-filter (== 5x5 min-erosion of z), separable in smem tiles
// ---------------------------------------------------------------------------
#define TILE 32
__global__ void minfilter_kernel() {
    __shared__ unsigned int s[36][36 + 1];
    __shared__ unsigned int h[36][TILE + 1];

    int b  = blockIdx.z;
    int ox = blockIdx.x * TILE;
    int oy = blockIdx.y * TILE;
    const unsigned int* pm = g_pm + b * HW;
    int t = threadIdx.y * blockDim.x + threadIdx.x;  // 256 threads

    for (int i = t; i < 36 * 36; i += 256) {
        int r = i / 36, c = i % 36;
        int gy = oy + r - 2, gx = ox + c - 2;
        unsigned int v = 0;  // OOB -> empty (identity for max)
        if (gy >= 0 && gy < IMG_H && gx >= 0 && gx < IMG_W) v = pm[gy * IMG_W + gx];
        s[r][c] = v;
    }
    __syncthreads();

    for (int i = t; i < 36 * TILE; i += 256) {
        int r = i / TILE, c = i % TILE;
        unsigned int v = s[r][c];
        v = max(v, s[r][c + 1]);
        v = max(v, s[r][c + 2]);
        v = max(v, s[r][c + 3]);
        v = max(v, s[r][c + 4]);
        h[r][c] = v;
    }
    __syncthreads();

    unsigned int* zo = g_zenc + b * HW;
    for (int i = t; i < TILE * TILE; i += 256) {
        int r = i / TILE, c = i % TILE;
        unsigned int v = h[r][c];
        v = max(v, h[r + 1][c]);
        v = max(v, h[r + 2][c]);
        v = max(v, h[r + 3][c]);
        v = max(v, h[r + 4][c]);
        zo[(oy + r) * IMG_W + (ox + c)] = v;
    }
}

// ---------------------------------------------------------------------------
// Pass 3: visibility (4 points/thread) + block-aggregated compaction.
// One global atomic per BLOCK (512 total); record order is irrelevant because
// the splat's atomics commute.
// ---------------------------------------------------------------------------
__global__ void vis_compact_kernel(const float4* __restrict__ pts4,
                                   const float* __restrict__ thr_p,
                                   float4* __restrict__ vis_out4) {
    // Grid is sized EXACTLY BN/4 threads: no early returns before barriers.
    int idx = blockIdx.x * blockDim.x + threadIdx.x;
    float4 a = pts4[3 * idx + 0];
    float4 b = pts4[3 * idx + 1];
    float4 c = pts4[3 * idx + 2];
    float thr = __ldg(thr_p);
    int bb = idx >> 14;
    const unsigned int* ze = g_zenc + bb * HW;

    float xs[4] = {a.x, a.w, b.z, c.y};
    float ys[4] = {a.y, b.x, b.w, c.z};
    float zs[4] = {a.z, b.y, c.x, c.w};
    bool vis[4];
    unsigned int cnt = 0;
    #pragma unroll
    for (int k = 0; k < 4; k++) {
        int px = (int)rintf(xs[k]);
        int py = (int)rintf(ys[k]);
        bool in_img = (px >= 0) && (px < IMG_W) && (py >= 0) && (py < IMG_H);
        bool v = false;
        if (in_img) {
            float zmin = __uint_as_float(~ze[py * IMG_W + px]);
            v = (zs[k] <= zmin + thr);
        }
        vis[k] = v;
        cnt += v ? 1u : 0u;
    }
    vis_out4[idx] = make_float4(vis[0] ? 1.f : 0.f, vis[1] ? 1.f : 0.f,
                                vis[2] ? 1.f : 0.f, vis[3] ? 1.f : 0.f);

    // warp inclusive scan of cnt
    unsigned int lane = threadIdx.x & 31u;
    unsigned int warp = threadIdx.x >> 5;
    unsigned int incl = cnt;
    #pragma unroll
    for (int d = 1; d < 32; d <<= 1) {
        unsigned int v = __shfl_up_sync(0xFFFFFFFFu, incl, d);
        if (lane >= d) incl += v;
    }
    unsigned int excl = incl - cnt;

    __shared__ unsigned int woff[8];
    __shared__ unsigned int blk_base;
    if (lane == 31u) woff[warp] = incl;   // warp total
    __syncthreads();
    if (threadIdx.x == 0) {
        unsigned int s = 0;
        #pragma unroll
        for (int w = 0; w < 8; w++) { unsigned int t = woff[w]; woff[w] = s; s += t; }
        blk_base = atomicAdd(&g_nvis, s);
    }
    __syncthreads();

    unsigned int slot = blk_base + woff[warp] + excl;
    #pragma unroll
    for (int k = 0; k < 4; k++) {
        if (vis[k]) {
            g_vlist[slot++] = make_float4(xs[k], ys[k], zs[k], __int_as_float(bb));
        }
    }
}

// ---------------------------------------------------------------------------
// Pass 4: dense splat, ONE THREAD PER (point, row, half-window): 16 threads
// per point (2 idle), 2 RED.128 each. Finer split = more warps for latency
// hiding, and the two half-window lanes of a row hit adjacent 64B (partial
// wavefront coalescing). Weights via rcp.approx (rel err ~1e-7, threshold is
// 1e-3). Zero-weight pad lanes add +0.0f; array padding absorbs overreach.
// Tail: also re-zeroes g_pm for the next graph replay (finish no longer does).
// ---------------------------------------------------------------------------
__global__ void splat_row_kernel() {
    int cnt = (int)g_nvis;
    int total = cnt << 4;               // 16 slots per point
    int stride = gridDim.x * blockDim.x;
    int tid0 = blockIdx.x * blockDim.x + threadIdx.x;

    for (int i = tid0; i < total; i += stride) {
        int sub = i & 15;
        int row = sub >> 1;             // 0..7
        if (row == 7) continue;         // idle lanes
        int half = sub & 1;
        int point = i >> 4;
        float4 r = __ldg(&g_vlist[point]);   // 16 lanes share the same 16B line
        float x = r.x, y = r.y, z = r.z;
        int bb = __float_as_int(r.w);
        int px = (int)rintf(x);
        int py = (int)rintf(y);

        int ii = py + row - 3;
        if (ii < 0 || ii >= IMG_H) continue;

        float dy = y - (float)ii;
        float dy2 = dy * dy;
        int jstart = ((px - 3) & ~1) + 4 * half;   // this thread's 4-col window
        float2* rowp = DW_BASE + bb * HW + ii * IMG_W + jstart;

        float ww[4];
        #pragma unroll
        for (int cc = 0; cc < 4; cc++) {
            int jj = jstart + cc;
            float dx = x - (float)jj;
            bool ok = (jj >= px - 3) && (jj <= px + 3) && (jj >= 0) && (jj < IMG_W);
            ww[cc] = ok ? fast_rcp(dx * dx + dy2 + EPSF) : 0.0f;
        }
        atomicAdd((float4*)(rowp + 0), make_float4(ww[0] * z, ww[0], ww[1] * z, ww[1]));
        atomicAdd((float4*)(rowp + 2), make_float4(ww[2] * z, ww[2], ww[3] * z, ww[3]));
    }

    // Tail work: reset g_pm (consumed by minfilter earlier this call) so the
    // next graph replay starts from the "empty" encoding.
    uint4 zu = make_uint4(0u, 0u, 0u, 0u);
    for (int j = tid0; j < BHW / 4; j += stride) {
        ((uint4*)g_pm)[j] = zu;
    }
}

// ---------------------------------------------------------------------------
// Pass 5: de-interleave accumulator (8 px/thread, MLP=4) + reset dw scratch
// ---------------------------------------------------------------------------
__global__ void finish_kernel(float* __restrict__ out) {
    int i = blockIdx.x * blockDim.x + threadIdx.x;  // one thread = 8 pixels
    if (i >= BHW / 8) return;
    const float4* dw = (const float4*)DW_BASE;      // 16B aligned
    float4 f0 = dw[4 * i + 0];
    float4 f1 = dw[4 * i + 1];
    float4 f2 = dw[4 * i + 2];
    float4 f3 = dw[4 * i + 3];
    ((float4*)out)[2 * i + 0]         = make_float4(f0.x, f0.z, f1.x, f1.z);  // depth
    ((float4*)out)[2 * i + 1]         = make_float4(f2.x, f2.z, f3.x, f3.z);
    ((float4*)(out + BHW))[2 * i + 0] = make_float4(f0.y, f0.w, f1.y, f1.w);  // weight
    ((float4*)(out + BHW))[2 * i + 1] = make_float4(f2.y, f2.w, f3.y, f3.w);
    float4 zf = make_float4(0.f, 0.f, 0.f, 0.f);
    ((float4*)DW_BASE)[4 * i + 0] = zf;
    ((float4*)DW_BASE)[4 * i + 1] = zf;
    ((float4*)DW_BASE)[4 * i + 2] = zf;
    ((float4*)DW_BASE)[4 * i + 3] = zf;
    if (i == 0) g_nvis = 0u;
}

// ---------------------------------------------------------------------------
extern "C" void kernel_launch(void* const* d_in, const int* in_sizes, int n_in,
                              void* d_out, int out_size) {
    const float* pts = (const float*)d_in[0];   // [B, N, 3]
    const float* thr = (const float*)d_in[1];   // scalar
    float* out = (float*)d_out;                 // [depth | weight | is_visible]

    const int T = 256;
    scatter_pm_kernel<<<BN / 4 / T, T>>>((const float4*)pts);
    dim3 fgrid(IMG_W / TILE, IMG_H / TILE, NB);
    minfilter_kernel<<<fgrid, dim3(32, 8)>>>();
    vis_compact_kernel<<<BN / 4 / T, T>>>((const float4*)pts, thr,
                                          (float4*)(out + 2 * BHW));
    splat_row_kernel<<<4096, T>>>();
    finish_kernel<<<BHW / 8 / T, T>>>(out);
}